// round 6
// baseline (speedup 1.0000x reference)
#include <cuda_runtime.h>
#include <cuda_bf16.h>
#include <cstdint>

// GlobalPoolDistance: patch-RBF MMD, single fused persistent kernel.
// MMA computes the exp2 argument directly:
//   A row i = [C2*a_0..C2*a_26, 1, -u_i, 0..]   (u = ||a||^2 * log2e/SIG2)
//   B row j = [b_0..b_26,      -v_j, 1, 0..]
//   acc(i,j) = C2*<a,b> - u - v = -log2e*||a-b||^2/SIG2 ;  K = exp2(acc).
// Phase 1: all CTAs stage bf16 operand rows (pre-swizzled).  Grid barrier.
// Phase 2: work-steal 4-tile chunks; A frags register-resident; B cp.async
// double-buffered.  Phase 3: last-done block reduces partials, writes out,
// resets counters (deterministic across graph replays).

#define TILE 128
#define NPATCH 3844
#define NTILES 31
#define NROWS (NTILES * TILE)                     // 3968
#define BATCH 8
#define ROW_U4 4
#define STAGE_U4 (4 * BATCH * NROWS * ROW_U4)
#define XY_CHUNKS 1984
#define SYM_CHUNKS_PER 136
#define CHUNKS (XY_CHUNKS + 16 * SYM_CHUNKS_PER) // 4160
#define WORKERS 296
#define STAGE_TASKS (2 * BATCH * NROWS)          // 63488

__device__ uint4 g_stage[STAGE_U4];
__device__ float g_partials[WORKERS];
__device__ unsigned int g_bar1;
__device__ unsigned int g_ticket;
__device__ unsigned int g_done;

__device__ __forceinline__ uint32_t smem_to_u32(const void* p) {
    uint32_t a;
    asm("{ .reg .u64 t; cvta.to.shared.u64 t, %1; cvt.u32.u64 %0, t; }"
        : "=r"(a) : "l"(p));
    return a;
}
__device__ __forceinline__ void cp_async16(uint32_t smem, const void* gptr) {
    asm volatile("cp.async.cg.shared.global [%0], [%1], 16;"
                 :: "r"(smem), "l"(gptr) : "memory");
}
#define CP_COMMIT() asm volatile("cp.async.commit_group;" ::: "memory")
#define CP_WAIT0()  asm volatile("cp.async.wait_group 0;" ::: "memory")

__device__ __forceinline__ void ldsm_x4(uint32_t& r0, uint32_t& r1,
                                        uint32_t& r2, uint32_t& r3, uint32_t a) {
    asm volatile("ldmatrix.sync.aligned.m8n8.x4.shared.b16 {%0,%1,%2,%3}, [%4];"
                 : "=r"(r0), "=r"(r1), "=r"(r2), "=r"(r3) : "r"(a));
}
__device__ __forceinline__ void mma16816(float* d,
                                         uint32_t a0, uint32_t a1, uint32_t a2, uint32_t a3,
                                         uint32_t b0, uint32_t b1) {
    asm volatile("mma.sync.aligned.m16n8k16.row.col.f32.bf16.bf16.f32 "
                 "{%0,%1,%2,%3}, {%4,%5,%6,%7}, {%8,%9}, {%0,%1,%2,%3};"
                 : "+f"(d[0]), "+f"(d[1]), "+f"(d[2]), "+f"(d[3])
                 : "r"(a0), "r"(a1), "r"(a2), "r"(a3), "r"(b0), "r"(b1));
}

struct __align__(1024) Smem {
    uint4 A[512];          // 8 KB A tile
    uint4 B[2][512];       // 2 x 8 KB B double buffer
    float red[8];
    unsigned int ticket;
    unsigned int lastflag;
};

__global__ void __launch_bounds__(256, 2)
mmd_fused(const float* __restrict__ x, const float* __restrict__ y,
          float* __restrict__ out) {
    __shared__ Smem sm;
    const int tid = threadIdx.x;
    const int wid = tid >> 5;
    const int lane = tid & 31;

    const float K1f = 4.9479492581208223f;        // log2e / 0.2916
    const float C2f = 9.8958985162416446f;        // 2*log2e / 0.2916

    // ================= Phase 1: stage operand rows =================
    {
        int gtid = blockIdx.x * 256 + tid;
        if (gtid < STAGE_TASKS) {
            int n = gtid % NROWS;
            int t2 = gtid / NROWS;                // 0..15
            int b = t2 & 7;
            int img = t2 >> 3;
            const float* im = img ? y : x;

            float rv[27];
            float u = 0.0f;
            bool valid = (n < NPATCH);
            if (valid) {
                int i = n / 62;
                int j = n - i * 62;
                const float* p = im + b * 12288 + (i << 6) + j;
                float sq = 0.0f;
                #pragma unroll
                for (int c = 0; c < 3; c++)
                    #pragma unroll
                    for (int rr = 0; rr < 3; rr++)
                        #pragma unroll
                        for (int ss = 0; ss < 3; ss++) {
                            float v = p[c * 4096 + (rr << 6) + ss];
                            sq = fmaf(v, v, sq);
                            rv[c * 9 + rr * 3 + ss] = v;
                        }
                u = sq * K1f;
            } else {
                #pragma unroll
                for (int k = 0; k < 27; k++) rv[k] = 0.0f;
            }
            uint32_t sw = (uint32_t)(n >> 1) & 3u;

            #pragma unroll
            for (int form = 0; form < 2; form++) {  // 0 = A-form, 1 = B-form
                float rowv[32];
                #pragma unroll
                for (int k = 0; k < 27; k++)
                    rowv[k] = form ? rv[k] : (C2f * rv[k]);
                float nu = valid ? -u : -1e30f;
                if (form) { rowv[27] = nu;   rowv[28] = 1.0f; }
                else      { rowv[27] = 1.0f; rowv[28] = nu;   }
                rowv[29] = rowv[30] = rowv[31] = 0.0f;
                uint32_t wds[16];
                #pragma unroll
                for (int q = 0; q < 16; q++) {
                    __nv_bfloat162 h2 = __floats2bfloat162_rn(rowv[2*q], rowv[2*q+1]);
                    wds[q] = *reinterpret_cast<uint32_t*>(&h2);
                }
                int ver = form * 2 + img;
                int base = ((ver * BATCH + b) * NROWS + n) * ROW_U4;
                #pragma unroll
                for (int c = 0; c < 4; c++)
                    g_stage[base + (c ^ sw)] =
                        make_uint4(wds[4*c], wds[4*c+1], wds[4*c+2], wds[4*c+3]);
            }
        }
        __threadfence();
        __syncthreads();
        if (tid == 0) {
            atomicAdd(&g_bar1, 1u);
            unsigned int v;
            do {
                asm volatile("ld.acquire.gpu.global.u32 %0, [%1];"
                             : "=r"(v) : "l"(&g_bar1));
                if (v >= WORKERS) break;
                __nanosleep(64);
            } while (true);
        }
        __syncthreads();
        __threadfence();
    }

    // ================= Phase 2: persistent tile loop =================
    const int mg = wid & 3;
    const int ng = wid >> 2;
    const uint32_t a_base  = smem_to_u32(sm.A);
    const uint32_t b_base0 = smem_to_u32(sm.B[0]);
    const uint32_t b_base1 = smem_to_u32(sm.B[1]);

    uint32_t offA[2][2];
    #pragma unroll
    for (int mt = 0; mt < 2; mt++)
        #pragma unroll
        for (int k = 0; k < 2; k++) {
            int rowA = mg * 32 + mt * 16 + (lane & 15);
            int ch = k * 2 + (lane >> 4);
            int swz = ch ^ ((rowA >> 1) & 3);
            offA[mt][k] = (uint32_t)(rowA * 64 + swz * 16);
        }
    uint32_t offB[2];
    #pragma unroll
    for (int k = 0; k < 2; k++) {
        int rloc = (lane & 7) + ((lane >> 4) << 3);
        int rowB = ng * 64 + rloc;
        int ch = k * 2 + ((lane >> 3) & 1);
        int swz = ch ^ ((rowB >> 1) & 3);
        offB[k] = (uint32_t)(rowB * 64 + swz * 16);
    }

    float s = 0.0f;

    for (;;) {
        __syncthreads();
        if (tid == 0) sm.ticket = atomicAdd(&g_ticket, 1u);
        __syncthreads();
        unsigned int c = sm.ticket;
        if (c >= CHUNKS) break;

        // ---- decode 4-tile chunk ----
        int ti, tj0, len, verA, verB, b;
        bool sym;
        if (c < XY_CHUNKS) {
            int seg = c >> 3, q = c & 7;
            b = seg / 31; ti = seg - b * 31;
            tj0 = q * 4; len = min(4, 31 - tj0);
            sym = false; verA = 0; verB = 3;
        } else {
            int d = (int)c - XY_CHUNKS;
            int g = d / SYM_CHUNKS_PER;
            int r = d - g * SYM_CHUNKS_PER;
            int kind = g >> 3; b = g & 7;
            int a = (int)((sqrtf(2.0f * (float)r + 1.0f) - 1.0f) * 0.5f);
            while (2 * (a + 1) * (a + 2) <= r) a++;
            while (a > 0 && 2 * a * (a + 1) > r) a--;
            int rr = r - 2 * a * (a + 1);
            int rig = rr / (a + 1);
            int cidx = rr - rig * (a + 1);
            ti = 4 * a + rig;
            tj0 = 4 * cidx;
            len = min(4, ti + 1 - tj0);
            sym = true; verA = kind; verB = 2 + kind;
        }

        // ---- A tile + first B tile ----
        {
            const uint4* asrc = g_stage + ((verA * BATCH + b) * NROWS + ti * TILE) * ROW_U4;
            cp_async16(a_base + (uint32_t)(tid * 16), asrc + tid);
            cp_async16(a_base + (uint32_t)((tid + 256) * 16), asrc + tid + 256);
            const uint4* bsrc = g_stage + ((verB * BATCH + b) * NROWS + tj0 * TILE) * ROW_U4;
            cp_async16(b_base0 + (uint32_t)(tid * 16), bsrc + tid);
            cp_async16(b_base0 + (uint32_t)((tid + 256) * 16), bsrc + tid + 256);
            CP_COMMIT();
        }

        uint32_t af[2][2][4];
        for (int j = 0; j < len; j++) {
            CP_WAIT0();
            __syncthreads();
            if (j + 1 < len) {
                uint32_t nb = ((j + 1) & 1) ? b_base1 : b_base0;
                const uint4* bsrc = g_stage +
                    ((verB * BATCH + b) * NROWS + (tj0 + j + 1) * TILE) * ROW_U4;
                cp_async16(nb + (uint32_t)(tid * 16), bsrc + tid);
                cp_async16(nb + (uint32_t)((tid + 256) * 16), bsrc + tid + 256);
                CP_COMMIT();
            }
            if (j == 0) {
                #pragma unroll
                for (int mt = 0; mt < 2; mt++)
                    #pragma unroll
                    for (int k = 0; k < 2; k++)
                        ldsm_x4(af[mt][k][0], af[mt][k][1], af[mt][k][2], af[mt][k][3],
                                a_base + offA[mt][k]);
            }

            const uint32_t bb = (j & 1) ? b_base1 : b_base0;
            float acc[2][8][4];
            #pragma unroll
            for (int mt = 0; mt < 2; mt++)
                #pragma unroll
                for (int nt = 0; nt < 8; nt++)
                    #pragma unroll
                    for (int r = 0; r < 4; r++) acc[mt][nt][r] = 0.0f;

            #pragma unroll
            for (int k = 0; k < 2; k++)
                #pragma unroll
                for (int p = 0; p < 4; p++) {
                    uint32_t b0, b1, b2, b3;
                    ldsm_x4(b0, b1, b2, b3, bb + offB[k] + (uint32_t)(p * 1024));
                    mma16816(acc[0][2*p],   af[0][k][0], af[0][k][1], af[0][k][2], af[0][k][3], b0, b1);
                    mma16816(acc[0][2*p+1], af[0][k][0], af[0][k][1], af[0][k][2], af[0][k][3], b2, b3);
                    mma16816(acc[1][2*p],   af[1][k][0], af[1][k][1], af[1][k][2], af[1][k][3], b0, b1);
                    mma16816(acc[1][2*p+1], af[1][k][0], af[1][k][1], af[1][k][2], af[1][k][3], b2, b3);
                }

            // ---- guard: 4 running max chains (low register pressure) ----
            float c0 = -3e38f, c1 = -3e38f, c2 = -3e38f, c3 = -3e38f;
            #pragma unroll
            for (int mt = 0; mt < 2; mt++)
                #pragma unroll
                for (int nt = 0; nt < 8; nt++) {
                    c0 = fmaxf(c0, acc[mt][nt][0]);
                    c1 = fmaxf(c1, acc[mt][nt][1]);
                    c2 = fmaxf(c2, acc[mt][nt][2]);
                    c3 = fmaxf(c3, acc[mt][nt][3]);
                }
            float mx = fmaxf(fmaxf(c0, c1), fmaxf(c2, c3));

            if (__any_sync(0xffffffffu, mx > -120.0f)) {
                int tj = tj0 + j;
                bool diagTile = sym && (tj == ti);
                float w = sym ? ((tj == ti) ? 1.0f : 2.0f) : -2.0f;
                int rbase = mg * 32 + (lane >> 2);
                int cbase = ng * 64 + ((lane & 3) << 1);
                float ts = 0.0f;
                #pragma unroll
                for (int mt = 0; mt < 2; mt++)
                    #pragma unroll
                    for (int nt = 0; nt < 8; nt++)
                        #pragma unroll
                        for (int r = 0; r < 4; r++) {
                            int rloc = rbase + mt * 16 + ((r >> 1) << 3);
                            int cloc = cbase + nt * 8 + (r & 1);
                            bool isd = diagTile && (rloc == cloc) &&
                                       (ti * TILE + rloc < NPATCH);
                            float e;
                            asm("ex2.approx.ftz.f32 %0, %1;" : "=f"(e)
                                : "f"(acc[mt][nt][r]));
                            ts += isd ? 1.0f : e;
                        }
                s = fmaf(w, ts, s);
            }
        }
    }

    // ================= Phase 3: reduce + finalize =================
    #pragma unroll
    for (int o = 16; o; o >>= 1) s += __shfl_xor_sync(0xffffffffu, s, o);
    if (lane == 0) sm.red[wid] = s;
    __syncthreads();
    if (tid == 0) {
        float tot = 0.0f;
        #pragma unroll
        for (int i2 = 0; i2 < 8; i2++) tot += sm.red[i2];
        g_partials[blockIdx.x] = tot;
        __threadfence();
        unsigned int old = atomicAdd(&g_done, 1u);
        sm.lastflag = (old == WORKERS - 1) ? 1u : 0u;
    }
    __syncthreads();
    if (sm.lastflag) {
        __threadfence();
        // parallel deterministic sum of 296 partials
        float v = 0.0f;
        for (int i = tid; i < WORKERS; i += 256) v += g_partials[i];
        #pragma unroll
        for (int o = 16; o; o >>= 1) v += __shfl_xor_sync(0xffffffffu, v, o);
        if (lane == 0) sm.red[wid] = v;
        __syncthreads();
        if (tid == 0) {
            float tot = 0.0f;
            #pragma unroll
            for (int i2 = 0; i2 < 8; i2++) tot += sm.red[i2];
            out[0] = tot * (float)(1.0 / (8.0 * 3844.0 * 3844.0));
            // reset counters for the next (graph-replayed) launch
            g_bar1 = 0u;
            g_ticket = 0u;
            __threadfence();
            g_done = 0u;
        }
    }
}

extern "C" void kernel_launch(void* const* d_in, const int* in_sizes, int n_in,
                              void* d_out, int out_size) {
    const float* x = (const float*)d_in[0];
    const float* y = (const float*)d_in[1];
    mmd_fused<<<WORKERS, 256>>>(x, y, (float*)d_out);
}

// round 7
// speedup vs baseline: 1.5232x; 1.5232x over previous
#include <cuda_runtime.h>
#include <cuda_bf16.h>
#include <cstdint>

// GlobalPoolDistance: patch-RBF MMD, single fused persistent kernel.
// MMA computes the exp2 argument directly:
//   A row i = [C2*a_0..C2*a_26, 1, -u_i, 0..]   (u = ||a||^2 * log2e/SIG2)
//   B row j = [b_0..b_26,      -v_j, 1, 0..]
//   acc(i,j) = C2*<a,b> - u - v = -log2e*||a-b||^2/SIG2 ;  K = exp2(acc).
// Epilogue skip threshold is -30: dropped terms are each <= 2^-30, so even
// dropping ALL off-diagonal pairs changes the weighted sum (~6.2e4) by
// <= 2.45e8 * 2^-30 = 0.23 -> rel err <= 3.7e-6 (deterministic bound).
// In practice only sym-diagonal tiles trigger the exp path (~3% of tiles).

#define TILE 128
#define NPATCH 3844
#define NTILES 31
#define NROWS (NTILES * TILE)                     // 3968
#define BATCH 8
#define ROW_U4 4
#define STAGE_U4 (4 * BATCH * NROWS * ROW_U4)
#define XY_CHUNKS 1984
#define SYM_CHUNKS_PER 136
#define CHUNKS (XY_CHUNKS + 16 * SYM_CHUNKS_PER) // 4160
#define WORKERS 296
#define STAGE_TASKS (2 * BATCH * NROWS)          // 63488

__device__ uint4 g_stage[STAGE_U4];
__device__ float g_partials[WORKERS];
__device__ unsigned int g_bar1;
__device__ unsigned int g_ticket;
__device__ unsigned int g_done;

__device__ __forceinline__ uint32_t smem_to_u32(const void* p) {
    uint32_t a;
    asm("{ .reg .u64 t; cvta.to.shared.u64 t, %1; cvt.u32.u64 %0, t; }"
        : "=r"(a) : "l"(p));
    return a;
}
__device__ __forceinline__ void cp_async16(uint32_t smem, const void* gptr) {
    asm volatile("cp.async.cg.shared.global [%0], [%1], 16;"
                 :: "r"(smem), "l"(gptr) : "memory");
}
#define CP_COMMIT() asm volatile("cp.async.commit_group;" ::: "memory")
#define CP_WAIT0()  asm volatile("cp.async.wait_group 0;" ::: "memory")

__device__ __forceinline__ void ldsm_x4(uint32_t& r0, uint32_t& r1,
                                        uint32_t& r2, uint32_t& r3, uint32_t a) {
    asm volatile("ldmatrix.sync.aligned.m8n8.x4.shared.b16 {%0,%1,%2,%3}, [%4];"
                 : "=r"(r0), "=r"(r1), "=r"(r2), "=r"(r3) : "r"(a));
}
__device__ __forceinline__ void mma16816(float* d,
                                         uint32_t a0, uint32_t a1, uint32_t a2, uint32_t a3,
                                         uint32_t b0, uint32_t b1) {
    asm volatile("mma.sync.aligned.m16n8k16.row.col.f32.bf16.bf16.f32 "
                 "{%0,%1,%2,%3}, {%4,%5,%6,%7}, {%8,%9}, {%0,%1,%2,%3};"
                 : "+f"(d[0]), "+f"(d[1]), "+f"(d[2]), "+f"(d[3])
                 : "r"(a0), "r"(a1), "r"(a2), "r"(a3), "r"(b0), "r"(b1));
}

struct __align__(1024) Smem {
    uint4 A[512];          // 8 KB A tile
    uint4 B[2][512];       // 2 x 8 KB B double buffer
    float red[8];
    unsigned int ticket;
    unsigned int lastflag;
};

__global__ void __launch_bounds__(256, 2)
mmd_fused(const float* __restrict__ x, const float* __restrict__ y,
          float* __restrict__ out) {
    __shared__ Smem sm;
    const int tid = threadIdx.x;
    const int wid = tid >> 5;
    const int lane = tid & 31;

    const float K1f = 4.9479492581208223f;        // log2e / 0.2916
    const float C2f = 9.8958985162416446f;        // 2*log2e / 0.2916

    // ================= Phase 1: stage operand rows =================
    {
        int gtid = blockIdx.x * 256 + tid;
        if (gtid < STAGE_TASKS) {
            int n = gtid % NROWS;
            int t2 = gtid / NROWS;                // 0..15
            int b = t2 & 7;
            int img = t2 >> 3;
            const float* im = img ? y : x;

            float rv[27];
            float u = 0.0f;
            bool valid = (n < NPATCH);
            if (valid) {
                int i = n / 62;
                int j = n - i * 62;
                const float* p = im + b * 12288 + (i << 6) + j;
                float sq = 0.0f;
                #pragma unroll
                for (int c = 0; c < 3; c++)
                    #pragma unroll
                    for (int rr = 0; rr < 3; rr++)
                        #pragma unroll
                        for (int ss = 0; ss < 3; ss++) {
                            float v = p[c * 4096 + (rr << 6) + ss];
                            sq = fmaf(v, v, sq);
                            rv[c * 9 + rr * 3 + ss] = v;
                        }
                u = sq * K1f;
            } else {
                #pragma unroll
                for (int k = 0; k < 27; k++) rv[k] = 0.0f;
            }
            uint32_t sw = (uint32_t)(n >> 1) & 3u;

            #pragma unroll
            for (int form = 0; form < 2; form++) {  // 0 = A-form, 1 = B-form
                float rowv[32];
                #pragma unroll
                for (int k = 0; k < 27; k++)
                    rowv[k] = form ? rv[k] : (C2f * rv[k]);
                float nu = valid ? -u : -1e30f;
                if (form) { rowv[27] = nu;   rowv[28] = 1.0f; }
                else      { rowv[27] = 1.0f; rowv[28] = nu;   }
                rowv[29] = rowv[30] = rowv[31] = 0.0f;
                uint32_t wds[16];
                #pragma unroll
                for (int q = 0; q < 16; q++) {
                    __nv_bfloat162 h2 = __floats2bfloat162_rn(rowv[2*q], rowv[2*q+1]);
                    wds[q] = *reinterpret_cast<uint32_t*>(&h2);
                }
                int ver = form * 2 + img;
                int base = ((ver * BATCH + b) * NROWS + n) * ROW_U4;
                #pragma unroll
                for (int c = 0; c < 4; c++)
                    g_stage[base + (c ^ sw)] =
                        make_uint4(wds[4*c], wds[4*c+1], wds[4*c+2], wds[4*c+3]);
            }
        }
        __threadfence();
        __syncthreads();
        if (tid == 0) {
            atomicAdd(&g_bar1, 1u);
            unsigned int v;
            do {
                asm volatile("ld.acquire.gpu.global.u32 %0, [%1];"
                             : "=r"(v) : "l"(&g_bar1));
                if (v >= WORKERS) break;
                __nanosleep(64);
            } while (true);
        }
        __syncthreads();
        __threadfence();
    }

    // ================= Phase 2: persistent tile loop =================
    const int mg = wid & 3;
    const int ng = wid >> 2;
    const uint32_t a_base  = smem_to_u32(sm.A);
    const uint32_t b_base0 = smem_to_u32(sm.B[0]);
    const uint32_t b_base1 = smem_to_u32(sm.B[1]);

    uint32_t offA[2][2];
    #pragma unroll
    for (int mt = 0; mt < 2; mt++)
        #pragma unroll
        for (int k = 0; k < 2; k++) {
            int rowA = mg * 32 + mt * 16 + (lane & 15);
            int ch = k * 2 + (lane >> 4);
            int swz = ch ^ ((rowA >> 1) & 3);
            offA[mt][k] = (uint32_t)(rowA * 64 + swz * 16);
        }
    uint32_t offB[2];
    #pragma unroll
    for (int k = 0; k < 2; k++) {
        int rloc = (lane & 7) + ((lane >> 4) << 3);
        int rowB = ng * 64 + rloc;
        int ch = k * 2 + ((lane >> 3) & 1);
        int swz = ch ^ ((rowB >> 1) & 3);
        offB[k] = (uint32_t)(rowB * 64 + swz * 16);
    }

    float s = 0.0f;

    for (;;) {
        __syncthreads();
        if (tid == 0) sm.ticket = atomicAdd(&g_ticket, 1u);
        __syncthreads();
        unsigned int c = sm.ticket;
        if (c >= CHUNKS) break;

        // ---- decode 4-tile chunk ----
        int ti, tj0, len, verA, verB, b;
        bool sym;
        if (c < XY_CHUNKS) {
            int seg = c >> 3, q = c & 7;
            b = seg / 31; ti = seg - b * 31;
            tj0 = q * 4; len = min(4, 31 - tj0);
            sym = false; verA = 0; verB = 3;
        } else {
            int d = (int)c - XY_CHUNKS;
            int g = d / SYM_CHUNKS_PER;
            int r = d - g * SYM_CHUNKS_PER;
            int kind = g >> 3; b = g & 7;
            int a = (int)((sqrtf(2.0f * (float)r + 1.0f) - 1.0f) * 0.5f);
            while (2 * (a + 1) * (a + 2) <= r) a++;
            while (a > 0 && 2 * a * (a + 1) > r) a--;
            int rr = r - 2 * a * (a + 1);
            int rig = rr / (a + 1);
            int cidx = rr - rig * (a + 1);
            ti = 4 * a + rig;
            tj0 = 4 * cidx;
            len = min(4, ti + 1 - tj0);
            sym = true; verA = kind; verB = 2 + kind;
        }

        // ---- A tile + first B tile ----
        {
            const uint4* asrc = g_stage + ((verA * BATCH + b) * NROWS + ti * TILE) * ROW_U4;
            cp_async16(a_base + (uint32_t)(tid * 16), asrc + tid);
            cp_async16(a_base + (uint32_t)((tid + 256) * 16), asrc + tid + 256);
            const uint4* bsrc = g_stage + ((verB * BATCH + b) * NROWS + tj0 * TILE) * ROW_U4;
            cp_async16(b_base0 + (uint32_t)(tid * 16), bsrc + tid);
            cp_async16(b_base0 + (uint32_t)((tid + 256) * 16), bsrc + tid + 256);
            CP_COMMIT();
        }

        uint32_t af[2][2][4];
        for (int j = 0; j < len; j++) {
            CP_WAIT0();
            __syncthreads();
            if (j + 1 < len) {
                uint32_t nb = ((j + 1) & 1) ? b_base1 : b_base0;
                const uint4* bsrc = g_stage +
                    ((verB * BATCH + b) * NROWS + (tj0 + j + 1) * TILE) * ROW_U4;
                cp_async16(nb + (uint32_t)(tid * 16), bsrc + tid);
                cp_async16(nb + (uint32_t)((tid + 256) * 16), bsrc + tid + 256);
                CP_COMMIT();
            }
            if (j == 0) {
                #pragma unroll
                for (int mt = 0; mt < 2; mt++)
                    #pragma unroll
                    for (int k = 0; k < 2; k++)
                        ldsm_x4(af[mt][k][0], af[mt][k][1], af[mt][k][2], af[mt][k][3],
                                a_base + offA[mt][k]);
            }

            const uint32_t bb = (j & 1) ? b_base1 : b_base0;
            float acc[2][8][4];
            #pragma unroll
            for (int mt = 0; mt < 2; mt++)
                #pragma unroll
                for (int nt = 0; nt < 8; nt++)
                    #pragma unroll
                    for (int r = 0; r < 4; r++) acc[mt][nt][r] = 0.0f;

            #pragma unroll
            for (int k = 0; k < 2; k++)
                #pragma unroll
                for (int p = 0; p < 4; p++) {
                    uint32_t b0, b1, b2, b3;
                    ldsm_x4(b0, b1, b2, b3, bb + offB[k] + (uint32_t)(p * 1024));
                    mma16816(acc[0][2*p],   af[0][k][0], af[0][k][1], af[0][k][2], af[0][k][3], b0, b1);
                    mma16816(acc[0][2*p+1], af[0][k][0], af[0][k][1], af[0][k][2], af[0][k][3], b2, b3);
                    mma16816(acc[1][2*p],   af[1][k][0], af[1][k][1], af[1][k][2], af[1][k][3], b0, b1);
                    mma16816(acc[1][2*p+1], af[1][k][0], af[1][k][1], af[1][k][2], af[1][k][3], b2, b3);
                }

            // ---- guard: 4 running max chains (low register pressure) ----
            float c0 = -3e38f, c1 = -3e38f, c2 = -3e38f, c3 = -3e38f;
            #pragma unroll
            for (int mt = 0; mt < 2; mt++)
                #pragma unroll
                for (int nt = 0; nt < 8; nt++) {
                    c0 = fmaxf(c0, acc[mt][nt][0]);
                    c1 = fmaxf(c1, acc[mt][nt][1]);
                    c2 = fmaxf(c2, acc[mt][nt][2]);
                    c3 = fmaxf(c3, acc[mt][nt][3]);
                }
            float mx = fmaxf(fmaxf(c0, c1), fmaxf(c2, c3));

            // Threshold -30: dropped terms <= 2^-30 each; total drop <= 0.23
            // absolute vs ~6.2e4 sum (rel <= 3.7e-6). Triggers only on
            // sym-diagonal tiles (arg ~ 0 there) and astronomically rare
            // near-duplicate patch pairs.
            if (__any_sync(0xffffffffu, mx > -30.0f)) {
                int tj = tj0 + j;
                bool diagTile = sym && (tj == ti);
                float w = sym ? ((tj == ti) ? 1.0f : 2.0f) : -2.0f;
                int rbase = mg * 32 + (lane >> 2);
                int cbase = ng * 64 + ((lane & 3) << 1);
                float ts = 0.0f;
                #pragma unroll
                for (int mt = 0; mt < 2; mt++)
                    #pragma unroll
                    for (int nt = 0; nt < 8; nt++)
                        #pragma unroll
                        for (int r = 0; r < 4; r++) {
                            int rloc = rbase + mt * 16 + ((r >> 1) << 3);
                            int cloc = cbase + nt * 8 + (r & 1);
                            bool isd = diagTile && (rloc == cloc) &&
                                       (ti * TILE + rloc < NPATCH);
                            float e;
                            asm("ex2.approx.ftz.f32 %0, %1;" : "=f"(e)
                                : "f"(acc[mt][nt][r]));
                            ts += isd ? 1.0f : e;
                        }
                s = fmaf(w, ts, s);
            }
        }
    }

    // ================= Phase 3: reduce + finalize =================
    #pragma unroll
    for (int o = 16; o; o >>= 1) s += __shfl_xor_sync(0xffffffffu, s, o);
    if (lane == 0) sm.red[wid] = s;
    __syncthreads();
    if (tid == 0) {
        float tot = 0.0f;
        #pragma unroll
        for (int i2 = 0; i2 < 8; i2++) tot += sm.red[i2];
        g_partials[blockIdx.x] = tot;
        __threadfence();
        unsigned int old = atomicAdd(&g_done, 1u);
        sm.lastflag = (old == WORKERS - 1) ? 1u : 0u;
    }
    __syncthreads();
    if (sm.lastflag) {
        __threadfence();
        // parallel deterministic sum of 296 partials
        float v = 0.0f;
        for (int i = tid; i < WORKERS; i += 256) v += g_partials[i];
        #pragma unroll
        for (int o = 16; o; o >>= 1) v += __shfl_xor_sync(0xffffffffu, v, o);
        if (lane == 0) sm.red[wid] = v;
        __syncthreads();
        if (tid == 0) {
            float tot = 0.0f;
            #pragma unroll
            for (int i2 = 0; i2 < 8; i2++) tot += sm.red[i2];
            out[0] = tot * (float)(1.0 / (8.0 * 3844.0 * 3844.0));
            // reset counters for the next (graph-replayed) launch
            g_bar1 = 0u;
            g_ticket = 0u;
            __threadfence();
            g_done = 0u;
        }
    }
}

extern "C" void kernel_launch(void* const* d_in, const int* in_sizes, int n_in,
                              void* d_out, int out_size) {
    const float* x = (const float*)d_in[0];
    const float* y = (const float*)d_in[1];
    mmd_fused<<<WORKERS, 256>>>(x, y, (float*)d_out);
}

// round 8
// speedup vs baseline: 1.6379x; 1.0753x over previous
#include <cuda_runtime.h>
#include <cuda_bf16.h>
#include <cstdint>

// GlobalPoolDistance: patch-RBF MMD, single fused persistent kernel.
// MMA computes the exp2 argument directly:
//   A row i = [C2*a_0..C2*a_26, 1, -u_i, 0..]   (u = ||a||^2 * log2e/SIG2)
//   B row j = [b_0..b_26,      -v_j, 1, 0..]
//   acc(i,j) = C2*<a,b> - u - v = -log2e*||a-b||^2/SIG2 ;  K = exp2(acc).
// Epilogue skip threshold -30 (deterministic bound: dropped terms each
// <= 2^-30; dropping ALL off-diag pairs shifts the ~6.2e4 sum by <= 0.23,
// rel <= 3.7e-6).  R8: 4-slot B ring with pair-processing (1 sync / 2 tiles),
// depth-6 guard max tree, 8-tile work-steal chunks.

#define TILE 128
#define NPATCH 3844
#define NTILES 31
#define NROWS (NTILES * TILE)                     // 3968
#define BATCH 8
#define ROW_U4 4
#define STAGE_U4 (4 * BATCH * NROWS * ROW_U4)
#define CHUNKS 2208                               // 992 xy + 1216 sym (len<=8)
#define WORKERS 296
#define STAGE_TASKS (2 * BATCH * NROWS)           // 63488

__device__ uint4 g_stage[STAGE_U4];
__device__ float g_partials[WORKERS];
__device__ unsigned int g_bar1;
__device__ unsigned int g_ticket;
__device__ unsigned int g_done;

__device__ __forceinline__ uint32_t smem_to_u32(const void* p) {
    uint32_t a;
    asm("{ .reg .u64 t; cvta.to.shared.u64 t, %1; cvt.u32.u64 %0, t; }"
        : "=r"(a) : "l"(p));
    return a;
}
__device__ __forceinline__ void cp_async16(uint32_t smem, const void* gptr) {
    asm volatile("cp.async.cg.shared.global [%0], [%1], 16;"
                 :: "r"(smem), "l"(gptr) : "memory");
}
#define CP_COMMIT() asm volatile("cp.async.commit_group;" ::: "memory")
#define CP_WAIT0()  asm volatile("cp.async.wait_group 0;" ::: "memory")

__device__ __forceinline__ void ldsm_x4(uint32_t& r0, uint32_t& r1,
                                        uint32_t& r2, uint32_t& r3, uint32_t a) {
    asm volatile("ldmatrix.sync.aligned.m8n8.x4.shared.b16 {%0,%1,%2,%3}, [%4];"
                 : "=r"(r0), "=r"(r1), "=r"(r2), "=r"(r3) : "r"(a));
}
__device__ __forceinline__ void mma16816(float* d,
                                         uint32_t a0, uint32_t a1, uint32_t a2, uint32_t a3,
                                         uint32_t b0, uint32_t b1) {
    asm volatile("mma.sync.aligned.m16n8k16.row.col.f32.bf16.bf16.f32 "
                 "{%0,%1,%2,%3}, {%4,%5,%6,%7}, {%8,%9}, {%0,%1,%2,%3};"
                 : "+f"(d[0]), "+f"(d[1]), "+f"(d[2]), "+f"(d[3])
                 : "r"(a0), "r"(a1), "r"(a2), "r"(a3), "r"(b0), "r"(b1));
}

struct __align__(1024) Smem {
    uint4 A[512];          // 8 KB A tile
    uint4 B[4][512];       // 4-slot B ring (pairs: slots {0,1} / {2,3})
    float red[8];
    unsigned int ticket;
    unsigned int lastflag;
};

__global__ void __launch_bounds__(256, 2)
mmd_fused(const float* __restrict__ x, const float* __restrict__ y,
          float* __restrict__ out) {
    __shared__ Smem sm;
    const int tid = threadIdx.x;
    const int wid = tid >> 5;
    const int lane = tid & 31;

    const float K1f = 4.9479492581208223f;        // log2e / 0.2916
    const float C2f = 9.8958985162416446f;        // 2*log2e / 0.2916

    // ================= Phase 1: stage operand rows =================
    {
        int gtid = blockIdx.x * 256 + tid;
        if (gtid < STAGE_TASKS) {
            int n = gtid % NROWS;
            int t2 = gtid / NROWS;
            int b = t2 & 7;
            int img = t2 >> 3;
            const float* im = img ? y : x;

            float rv[27];
            float u = 0.0f;
            bool valid = (n < NPATCH);
            if (valid) {
                int i = n / 62;
                int j = n - i * 62;
                const float* p = im + b * 12288 + (i << 6) + j;
                float sq = 0.0f;
                #pragma unroll
                for (int c = 0; c < 3; c++)
                    #pragma unroll
                    for (int rr = 0; rr < 3; rr++)
                        #pragma unroll
                        for (int ss = 0; ss < 3; ss++) {
                            float v = p[c * 4096 + (rr << 6) + ss];
                            sq = fmaf(v, v, sq);
                            rv[c * 9 + rr * 3 + ss] = v;
                        }
                u = sq * K1f;
            } else {
                #pragma unroll
                for (int k = 0; k < 27; k++) rv[k] = 0.0f;
            }
            uint32_t sw = (uint32_t)(n >> 1) & 3u;

            #pragma unroll
            for (int form = 0; form < 2; form++) {
                float rowv[32];
                #pragma unroll
                for (int k = 0; k < 27; k++)
                    rowv[k] = form ? rv[k] : (C2f * rv[k]);
                float nu = valid ? -u : -1e30f;
                if (form) { rowv[27] = nu;   rowv[28] = 1.0f; }
                else      { rowv[27] = 1.0f; rowv[28] = nu;   }
                rowv[29] = rowv[30] = rowv[31] = 0.0f;
                uint32_t wds[16];
                #pragma unroll
                for (int q = 0; q < 16; q++) {
                    __nv_bfloat162 h2 = __floats2bfloat162_rn(rowv[2*q], rowv[2*q+1]);
                    wds[q] = *reinterpret_cast<uint32_t*>(&h2);
                }
                int ver = form * 2 + img;
                int base = ((ver * BATCH + b) * NROWS + n) * ROW_U4;
                #pragma unroll
                for (int c = 0; c < 4; c++)
                    g_stage[base + (c ^ sw)] =
                        make_uint4(wds[4*c], wds[4*c+1], wds[4*c+2], wds[4*c+3]);
            }
        }
        __threadfence();
        __syncthreads();
        if (tid == 0) {
            atomicAdd(&g_bar1, 1u);
            unsigned int v;
            do {
                asm volatile("ld.acquire.gpu.global.u32 %0, [%1];"
                             : "=r"(v) : "l"(&g_bar1));
                if (v >= WORKERS) break;
                __nanosleep(64);
            } while (true);
        }
        __syncthreads();
        __threadfence();
    }

    // ================= Phase 2: persistent tile loop =================
    const int mg = wid & 3;
    const int ng = wid >> 2;
    const uint32_t a_base = smem_to_u32(sm.A);
    const uint32_t b_ring = smem_to_u32(sm.B);    // 4 slots x 8192 B

    uint32_t offA[2][2];
    #pragma unroll
    for (int mt = 0; mt < 2; mt++)
        #pragma unroll
        for (int k = 0; k < 2; k++) {
            int rowA = mg * 32 + mt * 16 + (lane & 15);
            int ch = k * 2 + (lane >> 4);
            int swz = ch ^ ((rowA >> 1) & 3);
            offA[mt][k] = (uint32_t)(rowA * 64 + swz * 16);
        }
    uint32_t offB[2];
    #pragma unroll
    for (int k = 0; k < 2; k++) {
        int rloc = (lane & 7) + ((lane >> 4) << 3);
        int rowB = ng * 64 + rloc;
        int ch = k * 2 + ((lane >> 3) & 1);
        int swz = ch ^ ((rowB >> 1) & 3);
        offB[k] = (uint32_t)(rowB * 64 + swz * 16);
    }

    float s = 0.0f;
    uint32_t af[2][2][4];

    // compute one 128x128 tile against B ring slot `slot`
    auto compute_tile = [&](int slot, int ti, int tj, bool sym) {
        const uint32_t bb = b_ring + (uint32_t)(slot * 8192);
        float acc[2][8][4];
        #pragma unroll
        for (int mt = 0; mt < 2; mt++)
            #pragma unroll
            for (int nt = 0; nt < 8; nt++)
                #pragma unroll
                for (int r = 0; r < 4; r++) acc[mt][nt][r] = 0.0f;

        #pragma unroll
        for (int k = 0; k < 2; k++)
            #pragma unroll
            for (int p = 0; p < 4; p++) {
                uint32_t b0, b1, b2, b3;
                ldsm_x4(b0, b1, b2, b3, bb + offB[k] + (uint32_t)(p * 1024));
                mma16816(acc[0][2*p],   af[0][k][0], af[0][k][1], af[0][k][2], af[0][k][3], b0, b1);
                mma16816(acc[0][2*p+1], af[0][k][0], af[0][k][1], af[0][k][2], af[0][k][3], b2, b3);
                mma16816(acc[1][2*p],   af[1][k][0], af[1][k][1], af[1][k][2], af[1][k][3], b0, b1);
                mma16816(acc[1][2*p+1], af[1][k][0], af[1][k][1], af[1][k][2], af[1][k][3], b2, b3);
            }

        // depth-6 max tree over the 64 args
        float t16[16];
        #pragma unroll
        for (int mt = 0; mt < 2; mt++)
            #pragma unroll
            for (int nt = 0; nt < 8; nt++)
                t16[mt * 8 + nt] = fmaxf(fmaxf(acc[mt][nt][0], acc[mt][nt][1]),
                                         fmaxf(acc[mt][nt][2], acc[mt][nt][3]));
        #pragma unroll
        for (int st = 8; st > 0; st >>= 1)
            #pragma unroll
            for (int i2 = 0; i2 < 8; i2++)
                if (i2 < st) t16[i2] = fmaxf(t16[i2], t16[i2 + st]);

        if (__any_sync(0xffffffffu, t16[0] > -30.0f)) {
            bool diagTile = sym && (tj == ti);
            float w = sym ? ((tj == ti) ? 1.0f : 2.0f) : -2.0f;
            int rbase = mg * 32 + (lane >> 2);
            int cbase = ng * 64 + ((lane & 3) << 1);
            float ts = 0.0f;
            #pragma unroll
            for (int mt = 0; mt < 2; mt++)
                #pragma unroll
                for (int nt = 0; nt < 8; nt++)
                    #pragma unroll
                    for (int r = 0; r < 4; r++) {
                        int rloc = rbase + mt * 16 + ((r >> 1) << 3);
                        int cloc = cbase + nt * 8 + (r & 1);
                        bool isd = diagTile && (rloc == cloc) &&
                                   (ti * TILE + rloc < NPATCH);
                        float e;
                        asm("ex2.approx.ftz.f32 %0, %1;" : "=f"(e)
                            : "f"(acc[mt][nt][r]));
                        ts += isd ? 1.0f : e;
                    }
            s = fmaf(w, ts, s);
        }
    };

    for (;;) {
        __syncthreads();
        if (tid == 0) sm.ticket = atomicAdd(&g_ticket, 1u);
        __syncthreads();
        unsigned int c = sm.ticket;
        if (c >= CHUNKS) break;

        // ---- decode 8-tile chunk ----
        int ti, tj0, len, verA, verB, b;
        bool sym;
        if (c < 992u) {
            int seg = c >> 2, q = c & 3;
            b = seg / 31; ti = seg - b * 31;
            tj0 = q * 8; len = (q < 3) ? 8 : 7;
            sym = false; verA = 0; verB = 3;
        } else {
            int d = (int)c - 992;
            int g = d / 76;
            int r = d - g * 76;
            int kind = g >> 3; b = g & 7;
            if (r < 8)       { ti = r;              tj0 = 0; }
            else if (r < 24) { int q = r - 8;  ti = 8  + (q >> 1); tj0 = (q & 1) * 8; }
            else if (r < 48) { int q = r - 24; int qd = q / 3; ti = 16 + qd; tj0 = (q - qd * 3) * 8; }
            else             { int q = r - 48; ti = 24 + (q >> 2); tj0 = (q & 3) * 8; }
            len = min(8, ti + 1 - tj0);
            sym = true; verA = kind; verB = 2 + kind;
        }

        const uint4* bbase = g_stage + ((verB * BATCH + b) * NROWS) * ROW_U4;

        // ---- prologue: A + first B pair (slots 0,1), one group ----
        {
            const uint4* asrc = g_stage + ((verA * BATCH + b) * NROWS + ti * TILE) * ROW_U4;
            cp_async16(a_base + (uint32_t)(tid * 16), asrc + tid);
            cp_async16(a_base + (uint32_t)((tid + 256) * 16), asrc + tid + 256);
            const uint4* b0src = bbase + (tj0 * TILE) * ROW_U4;
            cp_async16(b_ring + (uint32_t)(tid * 16), b0src + tid);
            cp_async16(b_ring + (uint32_t)((tid + 256) * 16), b0src + tid + 256);
            if (len > 1) {
                const uint4* b1src = bbase + ((tj0 + 1) * TILE) * ROW_U4;
                cp_async16(b_ring + (uint32_t)(8192 + tid * 16), b1src + tid);
                cp_async16(b_ring + (uint32_t)(8192 + (tid + 256) * 16), b1src + tid + 256);
            }
            CP_COMMIT();
        }

        bool afload = false;
        for (int jp = 0; jp < len; jp += 2) {
            CP_WAIT0();
            __syncthreads();                 // pair data visible; prev pair slots free
            int pg = (jp >> 1) & 1;          // this pair's slot group (0 or 1)
            if (jp + 2 < len) {              // prefetch next pair into other group
                int ng2 = pg ^ 1;
                uint32_t nb = b_ring + (uint32_t)(ng2 * 2 * 8192);
                const uint4* bs = bbase + ((tj0 + jp + 2) * TILE) * ROW_U4;
                cp_async16(nb + (uint32_t)(tid * 16), bs + tid);
                cp_async16(nb + (uint32_t)((tid + 256) * 16), bs + tid + 256);
                if (jp + 3 < len) {
                    const uint4* bs2 = bbase + ((tj0 + jp + 3) * TILE) * ROW_U4;
                    cp_async16(nb + (uint32_t)(8192 + tid * 16), bs2 + tid);
                    cp_async16(nb + (uint32_t)(8192 + (tid + 256) * 16), bs2 + tid + 256);
                }
                CP_COMMIT();
            }
            if (!afload) {
                #pragma unroll
                for (int mt = 0; mt < 2; mt++)
                    #pragma unroll
                    for (int k = 0; k < 2; k++)
                        ldsm_x4(af[mt][k][0], af[mt][k][1], af[mt][k][2], af[mt][k][3],
                                a_base + offA[mt][k]);
                afload = true;
            }
            compute_tile(pg * 2, ti, tj0 + jp, sym);
            if (jp + 1 < len)
                compute_tile(pg * 2 + 1, ti, tj0 + jp + 1, sym);
        }
    }

    // ================= Phase 3: reduce + finalize =================
    #pragma unroll
    for (int o = 16; o; o >>= 1) s += __shfl_xor_sync(0xffffffffu, s, o);
    if (lane == 0) sm.red[wid] = s;
    __syncthreads();
    if (tid == 0) {
        float tot = 0.0f;
        #pragma unroll
        for (int i2 = 0; i2 < 8; i2++) tot += sm.red[i2];
        g_partials[blockIdx.x] = tot;
        __threadfence();
        unsigned int old = atomicAdd(&g_done, 1u);
        sm.lastflag = (old == WORKERS - 1) ? 1u : 0u;
    }
    __syncthreads();
    if (sm.lastflag) {
        __threadfence();
        float v = 0.0f;
        for (int i = tid; i < WORKERS; i += 256) v += g_partials[i];
        #pragma unroll
        for (int o = 16; o; o >>= 1) v += __shfl_xor_sync(0xffffffffu, v, o);
        if (lane == 0) sm.red[wid] = v;
        __syncthreads();
        if (tid == 0) {
            float tot = 0.0f;
            #pragma unroll
            for (int i2 = 0; i2 < 8; i2++) tot += sm.red[i2];
            out[0] = tot * (float)(1.0 / (8.0 * 3844.0 * 3844.0));
            g_bar1 = 0u;
            g_ticket = 0u;
            __threadfence();
            g_done = 0u;
        }
    }
}

extern "C" void kernel_launch(void* const* d_in, const int* in_sizes, int n_in,
                              void* d_out, int out_size) {
    const float* x = (const float*)d_in[0];
    const float* y = (const float*)d_in[1];
    mmd_fused<<<WORKERS, 256>>>(x, y, (float*)d_out);
}